// round 5
// baseline (speedup 1.0000x reference)
#include <cuda_runtime.h>
#include <cstdint>
#include <math.h>

#define NN 1024
#define KK 512
#define TILE 128
#define KC 64              // k-chunk
#define NCH (KK / KC)      // 8 chunks
#define MARGIN 1.0f

#define PITCH 68                       // floats per smem row (pad 4: conflict-free frags)
#define PITCHB (PITCH * 4)             // 272 bytes
#define ABYTES (128 * PITCHB)          // 34816 per matrix per buffer
#define BUFB (2 * ABYTES)              // 69632 per buffer (A+B)
#define DYNB (2 * BUFB)                // 139264 total (double buffered)

// Scratch (device globals — allocation forbidden)
__device__ float g_dist[NN * NN];
__device__ float g_losses[NN];
__device__ unsigned int g_count;       // zero-init; self-resets each launch

// ---------------------------------------------------------------------------
static __device__ __forceinline__ uint32_t sptr(const void* p) {
    uint32_t a;
    asm("{ .reg .u64 t; cvta.to.shared.u64 t, %1; cvt.u32.u64 %0, t; }"
        : "=r"(a) : "l"(p));
    return a;
}
static __device__ __forceinline__ void cp16(uint32_t dst, const void* src) {
    asm volatile("cp.async.cg.shared.global [%0], [%1], 16;" :: "r"(dst), "l"(src));
}
#define CP_COMMIT() asm volatile("cp.async.commit_group;" ::: "memory")

static __device__ __forceinline__ void mma_tf32(
    float& d0, float& d1, float& d2, float& d3,
    float a0, float a1, float a2, float a3, float b0, float b1)
{
    asm volatile(
        "mma.sync.aligned.m16n8k8.row.col.f32.tf32.tf32.f32 "
        "{%0,%1,%2,%3}, {%4,%5,%6,%7}, {%8,%9}, {%0,%1,%2,%3};"
        : "+f"(d0), "+f"(d1), "+f"(d2), "+f"(d3)
        : "r"(__float_as_uint(a0)), "r"(__float_as_uint(a1)),
          "r"(__float_as_uint(a2)), "r"(__float_as_uint(a3)),
          "r"(__float_as_uint(b0)), "r"(__float_as_uint(b1)));
}

// ---------------------------------------------------------------------------
// Kernel 1: tf32 mma.sync distance GEMM, fused norms + sqrt epilogue.
// 64 CTAs (8x8 x 128x128), 128 threads = 4 warps, warp tile 64x64.
// ---------------------------------------------------------------------------
__global__ __launch_bounds__(128) void dist_mma_kernel(
    const float* __restrict__ X, float* __restrict__ D)
{
    extern __shared__ __align__(16) char dyn[];
    __shared__ float sqA_s[TILE], sqB_s[TILE];

    const int tid  = threadIdx.x;
    const int wid  = tid >> 5;
    const int lane = tid & 31;
    const int g    = lane >> 2;        // groupID
    const int tg   = lane & 3;         // thread-in-group
    const int bm   = (blockIdx.x >> 3) * TILE;
    const int bn   = (blockIdx.x & 7) * TILE;
    const int wm   = (wid >> 1) * 64;  // warp row offset in tile
    const int wn   = (wid & 1) * 64;   // warp col offset in tile

    const uint32_t smem = sptr(dyn);

    // ---- cp.async chunk issue: chunk c into buffer buf ----
    auto issue = [&](int c, int buf) {
        const uint32_t sb = smem + buf * BUFB;
        const float* XA = X + (size_t)bm * KK + c * KC;
        const float* XB = X + (size_t)bn * KK + c * KC;
#pragma unroll
        for (int it = 0; it < 16; it++) {
            int idx = tid + it * 128;          // 0..2047
            int row = idx >> 4;                // 0..127
            int kq  = idx & 15;                // 16B unit within 256B row-chunk
            uint32_t doff = row * PITCHB + kq * 16;
            cp16(sb + doff,          XA + (size_t)row * KK + kq * 4);
            cp16(sb + ABYTES + doff, XB + (size_t)row * KK + kq * 4);
        }
        CP_COMMIT();
    };

    issue(0, 0);
    issue(1, 1);

    float acc[4][8][4];
#pragma unroll
    for (int mt = 0; mt < 4; mt++)
#pragma unroll
        for (int nt = 0; nt < 8; nt++)
#pragma unroll
            for (int e = 0; e < 4; e++) acc[mt][nt][e] = 0.0f;

    float sa[4][2] = {};   // A-norm partials (wc==0 warps)
    float sb[8]    = {};   // B-norm partials (wr==0 warps)
    const bool awarp = ((wid & 1) == 0);
    const bool bwarp = (wid < 2);

    for (int c = 0; c < NCH; c++) {
        if (c < NCH - 1) asm volatile("cp.async.wait_group 1;" ::: "memory");
        else             asm volatile("cp.async.wait_group 0;" ::: "memory");
        __syncthreads();

        const int buf = c & 1;
        const float* As = (const float*)(dyn + buf * BUFB);
        const float* Bs = (const float*)(dyn + buf * BUFB + ABYTES);

#pragma unroll
        for (int s = 0; s < KC / 8; s++) {
            float a[4][4];
#pragma unroll
            for (int mt = 0; mt < 4; mt++) {
                const float* p = As + (wm + mt * 16 + g) * PITCH + s * 8 + tg;
                a[mt][0] = p[0];
                a[mt][2] = p[4];
                a[mt][1] = p[8 * PITCH];
                a[mt][3] = p[8 * PITCH + 4];
            }
            float b[8][2];
#pragma unroll
            for (int nt = 0; nt < 8; nt++) {
                const float* p = Bs + (wn + nt * 8 + g) * PITCH + s * 8 + tg;
                b[nt][0] = p[0];
                b[nt][1] = p[4];
            }
            if (awarp) {
#pragma unroll
                for (int mt = 0; mt < 4; mt++) {
                    sa[mt][0] += a[mt][0] * a[mt][0] + a[mt][2] * a[mt][2];
                    sa[mt][1] += a[mt][1] * a[mt][1] + a[mt][3] * a[mt][3];
                }
            }
            if (bwarp) {
#pragma unroll
                for (int nt = 0; nt < 8; nt++)
                    sb[nt] += b[nt][0] * b[nt][0] + b[nt][1] * b[nt][1];
            }
#pragma unroll
            for (int mt = 0; mt < 4; mt++)
#pragma unroll
                for (int nt = 0; nt < 8; nt++)
                    mma_tf32(acc[mt][nt][0], acc[mt][nt][1], acc[mt][nt][2], acc[mt][nt][3],
                             a[mt][0], a[mt][1], a[mt][2], a[mt][3],
                             b[nt][0], b[nt][1]);
        }
        __syncthreads();
        if (c + 2 < NCH) issue(c + 2, buf);
    }

    // ---- norm reduce: lanes sharing (g) cover all k residues; sum over tg ----
    if (awarp) {
#pragma unroll
        for (int mt = 0; mt < 4; mt++)
#pragma unroll
            for (int h = 0; h < 2; h++) {
                float v = sa[mt][h];
                v += __shfl_xor_sync(0xffffffffu, v, 1);
                v += __shfl_xor_sync(0xffffffffu, v, 2);
                if (tg == 0) sqA_s[wm + mt * 16 + h * 8 + g] = v;
            }
    }
    if (bwarp) {
#pragma unroll
        for (int nt = 0; nt < 8; nt++) {
            float v = sb[nt];
            v += __shfl_xor_sync(0xffffffffu, v, 1);
            v += __shfl_xor_sync(0xffffffffu, v, 2);
            if (tg == 0) sqB_s[wn + nt * 8 + g] = v;
        }
    }
    __syncthreads();

    // ---- epilogue: d = sqrt(relu(sqA + sqB - 2 dot)) ----
#pragma unroll
    for (int mt = 0; mt < 4; mt++) {
        const int r0 = wm + mt * 16 + g;
        const float sq0 = sqA_s[r0];
        const float sq1 = sqA_s[r0 + 8];
        const int gr = bm + r0;
#pragma unroll
        for (int nt = 0; nt < 8; nt++) {
            const int cc = wn + nt * 8 + 2 * tg;
            const float sb0 = sqB_s[cc], sb1 = sqB_s[cc + 1];
            float2 o0, o1;
            o0.x = sqrtf(fmaxf(sq0 + sb0 - 2.0f * acc[mt][nt][0], 0.0f));
            o0.y = sqrtf(fmaxf(sq0 + sb1 - 2.0f * acc[mt][nt][1], 0.0f));
            o1.x = sqrtf(fmaxf(sq1 + sb0 - 2.0f * acc[mt][nt][2], 0.0f));
            o1.y = sqrtf(fmaxf(sq1 + sb1 - 2.0f * acc[mt][nt][3], 0.0f));
            *(float2*)(D + (size_t)gr * NN + bn + cc) = o0;
            *(float2*)(D + (size_t)(gr + 8) * NN + bn + cc) = o1;
        }
    }
}

// ---------------------------------------------------------------------------
// Kernel 2: per-anchor triplet loss + fused final reduce (proven in R2)
// ---------------------------------------------------------------------------
__global__ __launch_bounds__(256) void anchor_loss_kernel(
    const float* __restrict__ D, const int* __restrict__ labels, int N,
    float* __restrict__ out)
{
    __shared__ float sh_neg[NN];
    __shared__ float sh_pos[NN];
    __shared__ int   sh_npos;
    __shared__ float red[256];
    __shared__ int   sh_islast;

    const int i = blockIdx.x;
    const int tid = threadIdx.x;
    const int li = labels[i];
    const float* row = D + (size_t)i * N;

    for (int j = tid; j < N; j += 256) {
        float d = __ldg(&row[j]);
        sh_neg[j] = (__ldg(&labels[j]) == li) ? 1.0e30f : d;
    }
    if (tid < 32) {
        int base = 0;
        for (int j0 = 0; j0 < N; j0 += 32) {
            int j = j0 + tid;
            int m = (__ldg(&labels[j]) == li);
            unsigned bal = __ballot_sync(0xffffffffu, m);
            if (m) {
                int pos = base + __popc(bal & ((1u << tid) - 1u));
                sh_pos[pos] = __ldg(&row[j]);
            }
            base += __popc(bal);
        }
        if (tid == 0) sh_npos = base;
    }
    __syncthreads();

    const int npos = sh_npos;
    float n0 = sh_neg[tid];
    float n1 = sh_neg[tid + 256];
    float n2 = sh_neg[tid + 512];
    float n3 = sh_neg[tid + 768];

    float sum = 0.0f;
    for (int p = 0; p < npos; p++) {
        float dp = sh_pos[p] + MARGIN;
        sum += fmaxf(dp - n0, 0.0f);
        sum += fmaxf(dp - n1, 0.0f);
        sum += fmaxf(dp - n2, 0.0f);
        sum += fmaxf(dp - n3, 0.0f);
    }

    red[tid] = sum;
    __syncthreads();
#pragma unroll
    for (int s = 128; s > 0; s >>= 1) {
        if (tid < s) red[tid] += red[tid + s];
        __syncthreads();
    }
    if (tid == 0) {
        g_losses[i] = red[0];
        __threadfence();
        unsigned v = atomicAdd(&g_count, 1u);
        sh_islast = (v == (unsigned)(gridDim.x - 1));
    }
    __syncthreads();

    if (sh_islast) {
        float s = 0.0f;
        for (int j = tid; j < N; j += 256) s += g_losses[j];
        red[tid] = s;
        __syncthreads();
#pragma unroll
        for (int st = 128; st > 0; st >>= 1) {
            if (tid < st) red[tid] += red[tid + st];
            __syncthreads();
        }
        if (tid == 0) {
            out[0] = red[0] / ((float)N + 1e-8f);
            g_count = 0u;
        }
    }
}

// ---------------------------------------------------------------------------
extern "C" void kernel_launch(void* const* d_in, const int* in_sizes, int n_in,
                              void* d_out, int out_size)
{
    const float* features = (const float*)d_in[0];
    const int*   labels   = (const int*)d_in[1];
    float*       out      = (float*)d_out;

    const int N = in_sizes[1];            // 1024

    float* D;
    cudaGetSymbolAddress((void**)&D, g_dist);

    cudaFuncSetAttribute(dist_mma_kernel,
                         cudaFuncAttributeMaxDynamicSharedMemorySize, DYNB);

    dist_mma_kernel<<<64, 128, DYNB>>>(features, D);
    anchor_loss_kernel<<<N, 256>>>(D, labels, N, out);
}

// round 7
// speedup vs baseline: 1.6772x; 1.6772x over previous
#include <cuda_runtime.h>
#include <cstdint>
#include <math.h>

#define NN 1024
#define KK 512
#define TILE 64            // CTA tile (square, triangular-symmetric)
#define KC 64              // k-chunk
#define NCH (KK / KC)      // 8
#define MARGIN 1.0f

#define PITCH 68           // floats per smem row (pad 4 -> conflict-free frags)
#define PITCHB (PITCH * 4) // 272 B
#define MATB (TILE * PITCHB)   // 17408 per matrix
#define BUFB (2 * MATB)        // 34816 per buffer (A+B)
#define DYNB (2 * BUFB)        // 69632 double-buffered

// Scratch (device globals — allocation forbidden)
__device__ float g_dist[NN * NN];
__device__ float g_losses[NN];
__device__ unsigned int g_count;   // zero-init; self-resets each launch

// ---------------------------------------------------------------------------
static __device__ __forceinline__ uint32_t sptr(const void* p) {
    uint32_t a;
    asm("{ .reg .u64 t; cvta.to.shared.u64 t, %1; cvt.u32.u64 %0, t; }"
        : "=r"(a) : "l"(p));
    return a;
}
static __device__ __forceinline__ void cp16(uint32_t dst, const void* src) {
    asm volatile("cp.async.cg.shared.global [%0], [%1], 16;" :: "r"(dst), "l"(src));
}
#define CP_COMMIT() asm volatile("cp.async.commit_group;" ::: "memory")

static __device__ __forceinline__ void mma_tf32(
    float& d0, float& d1, float& d2, float& d3,
    float a0, float a1, float a2, float a3, float b0, float b1)
{
    asm volatile(
        "mma.sync.aligned.m16n8k8.row.col.f32.tf32.tf32.f32 "
        "{%0,%1,%2,%3}, {%4,%5,%6,%7}, {%8,%9}, {%0,%1,%2,%3};"
        : "+f"(d0), "+f"(d1), "+f"(d2), "+f"(d3)
        : "r"(__float_as_uint(a0)), "r"(__float_as_uint(a1)),
          "r"(__float_as_uint(a2)), "r"(__float_as_uint(a3)),
          "r"(__float_as_uint(b0)), "r"(__float_as_uint(b1)));
}

// ---------------------------------------------------------------------------
// Kernel 1: tf32 mma.sync symmetric distance GEMM, fused norms + sqrt.
// 136 CTAs (triangular 64x64 tiles), 256 thr = 8 warps (2x4), warp tile 32x16.
// ---------------------------------------------------------------------------
__global__ __launch_bounds__(256) void dist_mma_kernel(
    const float* __restrict__ X, float* __restrict__ D)
{
    extern __shared__ __align__(16) char dyn[];
    __shared__ float sqA_s[TILE], sqB_s[TILE];

    const int tid  = threadIdx.x;
    const int wid  = tid >> 5;
    const int lane = tid & 31;
    const int g    = lane >> 2;
    const int tg   = lane & 3;

    // triangular block decode: row bi has (nb - bi) blocks
    const int nb = NN / TILE;          // 16
    int rem = blockIdx.x, bi = 0;
    while (rem >= nb - bi) { rem -= nb - bi; bi++; }
    const int bj = bi + rem;
    const int bm = bi * TILE;
    const int bn = bj * TILE;

    const int wm = (wid >> 2) * 32;    // 0 / 32
    const int wn = (wid & 3) * 16;     // 0..48

    const uint32_t smem = sptr(dyn);

    auto issue = [&](int c, int buf) {
        const uint32_t sb = smem + buf * BUFB;
        const float* XA = X + (size_t)bm * KK + c * KC;
        const float* XB = X + (size_t)bn * KK + c * KC;
#pragma unroll
        for (int it = 0; it < 4; it++) {
            int idx = tid + it * 256;        // 0..1023
            int row = idx >> 4;              // 0..63
            int kq  = idx & 15;
            uint32_t doff = row * PITCHB + kq * 16;
            cp16(sb + doff,        XA + (size_t)row * KK + kq * 4);
            cp16(sb + MATB + doff, XB + (size_t)row * KK + kq * 4);
        }
        CP_COMMIT();
    };

    issue(0, 0);
    issue(1, 1);

    float acc[2][2][4];
#pragma unroll
    for (int mt = 0; mt < 2; mt++)
#pragma unroll
        for (int nt = 0; nt < 2; nt++)
#pragma unroll
            for (int e = 0; e < 4; e++) acc[mt][nt][e] = 0.0f;

    float sa[2][2] = {};
    float sbn[2]   = {};
    const bool awarp = ((wid & 3) == 0);
    const bool bwarp = ((wid >> 2) == 0);

    for (int c = 0; c < NCH; c++) {
        if (c < NCH - 1) asm volatile("cp.async.wait_group 1;" ::: "memory");
        else             asm volatile("cp.async.wait_group 0;" ::: "memory");
        __syncthreads();

        const float* As = (const float*)(dyn + (c & 1) * BUFB);
        const float* Bs = (const float*)(dyn + (c & 1) * BUFB + MATB);

#pragma unroll
        for (int s = 0; s < KC / 8; s++) {
            float a[2][4];
#pragma unroll
            for (int mt = 0; mt < 2; mt++) {
                const float* p = As + (wm + mt * 16 + g) * PITCH + s * 8 + tg;
                a[mt][0] = p[0];
                a[mt][2] = p[4];
                a[mt][1] = p[8 * PITCH];
                a[mt][3] = p[8 * PITCH + 4];
            }
            float b[2][2];
#pragma unroll
            for (int nt = 0; nt < 2; nt++) {
                const float* p = Bs + (wn + nt * 8 + g) * PITCH + s * 8 + tg;
                b[nt][0] = p[0];
                b[nt][1] = p[4];
            }
            if (awarp) {
#pragma unroll
                for (int mt = 0; mt < 2; mt++) {
                    sa[mt][0] += a[mt][0] * a[mt][0] + a[mt][2] * a[mt][2];
                    sa[mt][1] += a[mt][1] * a[mt][1] + a[mt][3] * a[mt][3];
                }
            }
            if (bwarp) {
#pragma unroll
                for (int nt = 0; nt < 2; nt++)
                    sbn[nt] += b[nt][0] * b[nt][0] + b[nt][1] * b[nt][1];
            }
#pragma unroll
            for (int mt = 0; mt < 2; mt++)
#pragma unroll
                for (int nt = 0; nt < 2; nt++)
                    mma_tf32(acc[mt][nt][0], acc[mt][nt][1], acc[mt][nt][2], acc[mt][nt][3],
                             a[mt][0], a[mt][1], a[mt][2], a[mt][3],
                             b[nt][0], b[nt][1]);
        }
        __syncthreads();
        if (c + 2 < NCH) issue(c + 2, c & 1);
    }

    // fused-norm reduce over tg lanes
    if (awarp) {
#pragma unroll
        for (int mt = 0; mt < 2; mt++)
#pragma unroll
            for (int h = 0; h < 2; h++) {
                float v = sa[mt][h];
                v += __shfl_xor_sync(0xffffffffu, v, 1);
                v += __shfl_xor_sync(0xffffffffu, v, 2);
                if (tg == 0) sqA_s[wm + mt * 16 + h * 8 + g] = v;
            }
    }
    if (bwarp) {
#pragma unroll
        for (int nt = 0; nt < 2; nt++) {
            float v = sbn[nt];
            v += __shfl_xor_sync(0xffffffffu, v, 1);
            v += __shfl_xor_sync(0xffffffffu, v, 2);
            if (tg == 0) sqB_s[wn + nt * 8 + g] = v;
        }
    }
    __syncthreads();

    // epilogue: d = sqrt(relu(sqA + sqB - 2 dot)); store + mirror
    const bool offdiag = (bi != bj);
#pragma unroll
    for (int mt = 0; mt < 2; mt++) {
        const int r0 = wm + mt * 16 + g;
        const float sq0 = sqA_s[r0];
        const float sq1 = sqA_s[r0 + 8];
        const int gi0 = bm + r0, gi1 = gi0 + 8;
#pragma unroll
        for (int nt = 0; nt < 2; nt++) {
            const int cc = wn + nt * 8 + 2 * tg;
            const float sb0 = sqB_s[cc], sb1 = sqB_s[cc + 1];
            const int gj0 = bn + cc, gj1 = gj0 + 1;
            float2 o0, o1;
            o0.x = sqrtf(fmaxf(sq0 + sb0 - 2.0f * acc[mt][nt][0], 0.0f));
            o0.y = sqrtf(fmaxf(sq0 + sb1 - 2.0f * acc[mt][nt][1], 0.0f));
            o1.x = sqrtf(fmaxf(sq1 + sb0 - 2.0f * acc[mt][nt][2], 0.0f));
            o1.y = sqrtf(fmaxf(sq1 + sb1 - 2.0f * acc[mt][nt][3], 0.0f));
            *(float2*)(D + (size_t)gi0 * NN + gj0) = o0;
            *(float2*)(D + (size_t)gi1 * NN + gj0) = o1;
            if (offdiag) {
                D[(size_t)gj0 * NN + gi0] = o0.x;
                D[(size_t)gj1 * NN + gi0] = o0.y;
                D[(size_t)gj0 * NN + gi1] = o1.x;
                D[(size_t)gj1 * NN + gi1] = o1.y;
            }
        }
    }
}

// ---------------------------------------------------------------------------
// Kernel 2: per-anchor loss via sorted positives + binary search,
// plus fused final reduce (last block done).
// sum_p relu(dp - t) with t = nk - margin  ==  SS[idx] - (npos - idx) * t
// where idx = #{p : dp <= t}, SS = suffix sums of sorted positives.
// ---------------------------------------------------------------------------
__global__ __launch_bounds__(256) void anchor_loss_kernel(
    const float* __restrict__ D, const int* __restrict__ labels, int N,
    float* __restrict__ out)
{
    __shared__ float sh_neg[NN];
    __shared__ float sh_pos[256];
    __shared__ float sorted[256];
    __shared__ float ss[132];
    __shared__ int   sh_npos;
    __shared__ float red[256];
    __shared__ int   sh_islast;

    const int i = blockIdx.x;
    const int tid = threadIdx.x;
    const int li = labels[i];
    const float* row = D + (size_t)i * N;

    // classify; positives neutralized with big sentinel
    for (int j = tid; j < N; j += 256) {
        float d = __ldg(&row[j]);
        sh_neg[j] = (__ldg(&labels[j]) == li) ? 1.0e30f : d;
    }
    if (tid < 256) sorted[tid] = 3.0e30f;      // INF pad

    // warp 0: deterministic ballot compaction of positives
    if (tid < 32) {
        int base = 0;
        for (int j0 = 0; j0 < N; j0 += 32) {
            int j = j0 + tid;
            int m = (__ldg(&labels[j]) == li);
            unsigned bal = __ballot_sync(0xffffffffu, m);
            if (m) {
                int pos = base + __popc(bal & ((1u << tid) - 1u));
                sh_pos[pos] = __ldg(&row[j]);
            }
            base += __popc(bal);
        }
        if (tid == 0) sh_npos = base;
    }
    __syncthreads();

    const int npos = sh_npos;

    // stable rank sort (npos ~32, threads [0, npos))
    if (tid < npos) {
        float v = sh_pos[tid];
        int rank = 0;
        for (int j = 0; j < npos; j++) {
            float w = sh_pos[j];
            rank += (w < v) || (w == v && j < tid);
        }
        sorted[rank] = v;
    }
    __syncthreads();

    // warp 0: suffix sums over 128 slots (values beyond npos count as 0)
    if (tid < 32) {
        float v0 = (4 * tid + 0 < npos) ? sorted[4 * tid + 0] : 0.f;
        float v1 = (4 * tid + 1 < npos) ? sorted[4 * tid + 1] : 0.f;
        float v2 = (4 * tid + 2 < npos) ? sorted[4 * tid + 2] : 0.f;
        float v3 = (4 * tid + 3 < npos) ? sorted[4 * tid + 3] : 0.f;
        float s3 = v3, s2 = v2 + s3, s1 = v1 + s2, s0 = v0 + s1;
        float x = s0;                       // inclusive suffix over chunks
#pragma unroll
        for (int d = 1; d < 32; d <<= 1) {
            float y = __shfl_down_sync(0xffffffffu, x, d);
            if (tid + d < 32) x += y;
        }
        float carry = x - s0;               // chunks after this lane
        ss[4 * tid + 0] = s0 + carry;
        ss[4 * tid + 1] = s1 + carry;
        ss[4 * tid + 2] = s2 + carry;
        ss[4 * tid + 3] = s3 + carry;
        if (tid == 0) ss[128] = 0.f;
    }
    __syncthreads();

    // each thread: 4 negatives, branchless 7-step search over 128-padded array
    float sum = 0.0f;
#pragma unroll
    for (int q = 0; q < 4; q++) {
        float t = sh_neg[tid + q * 256] - MARGIN;
        int pos = 0;
#pragma unroll
        for (int s = 64; s > 0; s >>= 1)
            if (sorted[pos + s - 1] <= t) pos += s;
        sum += ss[pos] - (float)(npos - pos) * t;
    }

    red[tid] = sum;
    __syncthreads();
#pragma unroll
    for (int s = 128; s > 0; s >>= 1) {
        if (tid < s) red[tid] += red[tid + s];
        __syncthreads();
    }
    if (tid == 0) {
        g_losses[i] = red[0];
        __threadfence();
        unsigned v = atomicAdd(&g_count, 1u);
        sh_islast = (v == (unsigned)(gridDim.x - 1));
    }
    __syncthreads();

    if (sh_islast) {
        float s = 0.0f;
        for (int j = tid; j < N; j += 256) s += g_losses[j];
        red[tid] = s;
        __syncthreads();
#pragma unroll
        for (int st = 128; st > 0; st >>= 1) {
            if (tid < st) red[tid] += red[tid + st];
            __syncthreads();
        }
        if (tid == 0) {
            out[0] = red[0] / ((float)N + 1e-8f);
            g_count = 0u;
        }
    }
}

// ---------------------------------------------------------------------------
extern "C" void kernel_launch(void* const* d_in, const int* in_sizes, int n_in,
                              void* d_out, int out_size)
{
    const float* features = (const float*)d_in[0];
    const int*   labels   = (const int*)d_in[1];
    float*       out      = (float*)d_out;

    const int N = in_sizes[1];            // 1024

    float* D;
    cudaGetSymbolAddress((void**)&D, g_dist);

    cudaFuncSetAttribute(dist_mma_kernel,
                         cudaFuncAttributeMaxDynamicSharedMemorySize, DYNB);

    const int nb = NN / TILE;             // 16 -> 136 CTAs
    dist_mma_kernel<<<nb * (nb + 1) / 2, 256, DYNB>>>(features, D);
    anchor_loss_kernel<<<N, 256>>>(D, labels, N, out);
}